// round 1
// baseline (speedup 1.0000x reference)
#include <cuda_runtime.h>
#include <math.h>

// Problem shape (fixed by setup_inputs): B=4096, D=512, N=2B=8192, T=0.1
#define BHALF 4096
#define NROWS 8192
#define DDIM  512
#define INV_T 10.0f
#define MSHIFT 10.0f      // fixed logsumexp shift: max logit = 1/T = 10 (diagonal)
#define CSPLIT 4          // column splits for the big GEMM
#define COLS_PER_SPLIT (NROWS / CSPLIT)   // 2048

// GEMM tiling
#define BM 128
#define BN 128
#define BK 16
#define PITCH 132         // smem pitch (floats) to soften STS conflicts, 16B-aligned

// Scratch (allocation-free rule: __device__ globals)
__device__ float g_zn[NROWS * DDIM];            // normalized z, 16.8 MB
__device__ float g_spart[CSPLIT * NROWS];       // partial sum_j exp(sim-10) per split
__device__ float g_rowloss[NROWS];              // per-row (lse - pos)

// ---------------------------------------------------------------------------
// Kernel 1: normalize rows.  grid = NROWS blocks, 128 threads (4 floats each).
// ---------------------------------------------------------------------------
__global__ void ntx_normalize(const float* __restrict__ zi,
                              const float* __restrict__ zj) {
    const int row = blockIdx.x;
    const int t   = threadIdx.x;             // 0..127
    const float* src = (row < BHALF) ? (zi + (size_t)row * DDIM)
                                     : (zj + (size_t)(row - BHALF) * DDIM);
    float4 v = ((const float4*)src)[t];
    float ss = v.x*v.x + v.y*v.y + v.z*v.z + v.w*v.w;
    #pragma unroll
    for (int o = 16; o > 0; o >>= 1) ss += __shfl_xor_sync(0xffffffffu, ss, o);
    __shared__ float sw[4];
    if ((t & 31) == 0) sw[t >> 5] = ss;
    __syncthreads();
    float tot = sw[0] + sw[1] + sw[2] + sw[3];
    float scale = 1.0f / fmaxf(sqrtf(tot), 1e-12f);
    float4 o4 = make_float4(v.x*scale, v.y*scale, v.z*scale, v.w*scale);
    ((float4*)(g_zn + (size_t)row * DDIM))[t] = o4;
}

// ---------------------------------------------------------------------------
// Kernel 2: row-sum of exp(sim - 10) over a column split.
//   sim = (zn zn^T) * 10.  Diagonal contributes exactly exp(0)=1 (subtracted later).
//   grid = (NROWS/BM, CSPLIT), 256 threads, 8x8 register tile.
// ---------------------------------------------------------------------------
__global__ __launch_bounds__(256, 2) void ntx_gemm_expsum() {
    __shared__ float As[BK][PITCH];
    __shared__ float Bs[BK][PITCH];

    const int rb    = blockIdx.x * BM;       // row base
    const int split = blockIdx.y;
    const int tid   = threadIdx.x;
    const int tx    = tid & 15;              // 0..15 (col group)
    const int ty    = tid >> 4;              // 0..15 (row group)

    float rs[8];
    #pragma unroll
    for (int i = 0; i < 8; i++) rs[i] = 0.0f;

    for (int ct = 0; ct < COLS_PER_SPLIT / BN; ct++) {
        const int cb = split * COLS_PER_SPLIT + ct * BN;   // col base

        float acc[8][8];
        #pragma unroll
        for (int i = 0; i < 8; i++)
            #pragma unroll
            for (int j = 0; j < 8; j++) acc[i][j] = 0.0f;

        for (int kt = 0; kt < DDIM; kt += BK) {
            __syncthreads();   // protect previous tile / reduction buffer
            // Load BMxBK of A and B, transposed into smem [k][row].
            // 512 float4 per matrix, 2 per thread, coalesced in GMEM.
            #pragma unroll
            for (int m = 0; m < 2; m++) {
                const int f4 = tid + m * 256;    // 0..511
                const int r  = f4 >> 2;          // 0..127
                const int kq = (f4 & 3) << 2;    // 0,4,8,12
                float4 av = *(const float4*)&g_zn[(size_t)(rb + r) * DDIM + kt + kq];
                As[kq + 0][r] = av.x; As[kq + 1][r] = av.y;
                As[kq + 2][r] = av.z; As[kq + 3][r] = av.w;
                float4 bv = *(const float4*)&g_zn[(size_t)(cb + r) * DDIM + kt + kq];
                Bs[kq + 0][r] = bv.x; Bs[kq + 1][r] = bv.y;
                Bs[kq + 2][r] = bv.z; Bs[kq + 3][r] = bv.w;
            }
            __syncthreads();

            #pragma unroll
            for (int k = 0; k < BK; k++) {
                float a[8], b[8];
                *(float4*)&a[0] = *(const float4*)&As[k][ty * 8];
                *(float4*)&a[4] = *(const float4*)&As[k][ty * 8 + 4];
                *(float4*)&b[0] = *(const float4*)&Bs[k][tx * 8];
                *(float4*)&b[4] = *(const float4*)&Bs[k][tx * 8 + 4];
                #pragma unroll
                for (int i = 0; i < 8; i++)
                    #pragma unroll
                    for (int j = 0; j < 8; j++)
                        acc[i][j] = fmaf(a[i], b[j], acc[i][j]);
            }
        }

        // Epilogue: accumulate exp(acc*10 - 10) into per-row sums.
        #pragma unroll
        for (int i = 0; i < 8; i++) {
            float s = 0.0f;
            #pragma unroll
            for (int j = 0; j < 8; j++)
                s += __expf(fmaf(acc[i][j], INV_T, -MSHIFT));
            rs[i] += s;
        }
    }

    // Cross-thread reduction: 16 tx-partials per row. Reuse As as scratch.
    __syncthreads();
    float* red = &As[0][0];                   // 128*16 floats fits (16*132)
    #pragma unroll
    for (int i = 0; i < 8; i++) red[(ty * 8 + i) * 16 + tx] = rs[i];
    __syncthreads();
    if (tid < BM) {
        float s = 0.0f;
        #pragma unroll
        for (int x = 0; x < 16; x++) s += red[tid * 16 + x];
        g_spart[split * NROWS + rb + tid] = s;
    }
}

// ---------------------------------------------------------------------------
// Kernel 3: per-pair positive dot + per-row loss.
//   grid = BHALF blocks, 128 threads. Pair (p, p+B) shares the positive.
// ---------------------------------------------------------------------------
__global__ void ntx_pairloss() {
    const int p = blockIdx.x;                // 0..BHALF-1
    const int t = threadIdx.x;               // 0..127
    float4 a = ((const float4*)(g_zn + (size_t)p * DDIM))[t];
    float4 b = ((const float4*)(g_zn + (size_t)(p + BHALF) * DDIM))[t];
    float d = a.x*b.x + a.y*b.y + a.z*b.z + a.w*b.w;
    #pragma unroll
    for (int o = 16; o > 0; o >>= 1) d += __shfl_xor_sync(0xffffffffu, d, o);
    __shared__ float sw[4];
    if ((t & 31) == 0) sw[t >> 5] = d;
    __syncthreads();
    if (t == 0) {
        float dot = sw[0] + sw[1] + sw[2] + sw[3];
        float pos = dot * INV_T;
        float s0 = g_spart[0 * NROWS + p] + g_spart[1 * NROWS + p]
                 + g_spart[2 * NROWS + p] + g_spart[3 * NROWS + p] - 1.0f;
        int q = p + BHALF;
        float s1 = g_spart[0 * NROWS + q] + g_spart[1 * NROWS + q]
                 + g_spart[2 * NROWS + q] + g_spart[3 * NROWS + q] - 1.0f;
        g_rowloss[p] = MSHIFT + logf(s0) - pos;
        g_rowloss[q] = MSHIFT + logf(s1) - pos;
    }
}

// ---------------------------------------------------------------------------
// Kernel 4: mean over NROWS -> scalar out.
// ---------------------------------------------------------------------------
__global__ void ntx_reduce(float* __restrict__ out) {
    const int t = threadIdx.x;               // 256 threads
    float s = 0.0f;
    for (int i = t; i < NROWS; i += 256) s += g_rowloss[i];
    #pragma unroll
    for (int o = 16; o > 0; o >>= 1) s += __shfl_xor_sync(0xffffffffu, s, o);
    __shared__ float sw[8];
    if ((t & 31) == 0) sw[t >> 5] = s;
    __syncthreads();
    if (t == 0) {
        float tot = 0.0f;
        #pragma unroll
        for (int w = 0; w < 8; w++) tot += sw[w];
        out[0] = tot * (1.0f / (float)NROWS);
    }
}

// ---------------------------------------------------------------------------
extern "C" void kernel_launch(void* const* d_in, const int* in_sizes, int n_in,
                              void* d_out, int out_size) {
    const float* zi = (const float*)d_in[0];
    const float* zj = (const float*)d_in[1];
    float* out = (float*)d_out;
    (void)in_sizes; (void)n_in; (void)out_size;

    ntx_normalize<<<NROWS, 128>>>(zi, zj);
    ntx_gemm_expsum<<<dim3(NROWS / BM, CSPLIT), 256>>>();
    ntx_pairloss<<<BHALF, 128>>>();
    ntx_reduce<<<1, 256>>>(out);
}

// round 5
// speedup vs baseline: 4.2468x; 4.2468x over previous
#include <cuda_runtime.h>
#include <cuda_bf16.h>
#include <math.h>
#include <stdint.h>

// Problem shape (fixed): B=4096, D=512, N=2B=8192, T=0.1
#define BHALF 4096
#define NROWS 8192
#define DDIM  512
#define INV_T 10.0f
#define MSHIFT 10.0f
#define CSPLIT 2
#define COLS_PER_CTA (NROWS / CSPLIT)      // 4096
#define NT (COLS_PER_CTA / 128)            // 32 column tiles per CTA
#define NCHUNK (NT * 8)                    // 256 B chunks (128 rows x 64 K each)
#define NSTB 4                             // B ring stages

// Scratch (__device__ globals: allocation-free rule)
__device__ float         g_zn[NROWS * DDIM];     // fp32 normalized (positives)
__device__ __nv_bfloat16 g_zbf[NROWS * DDIM];    // bf16 normalized (GEMM)
__device__ float         g_spart[CSPLIT * NROWS];
__device__ float         g_rowloss[NROWS];

// ---------------- helpers ----------------
__device__ __forceinline__ uint32_t smem_u32(const void* p) {
    uint32_t a;
    asm("{ .reg .u64 t; cvta.to.shared.u64 t, %1; cvt.u32.u64 %0, t; }" : "=r"(a) : "l"(p));
    return a;
}
__device__ __forceinline__ void cpasync16(uint32_t dst, const void* src) {
    asm volatile("cp.async.cg.shared.global [%0], [%1], 16;" :: "r"(dst), "l"(src) : "memory");
}
#define CP_COMMIT() asm volatile("cp.async.commit_group;" ::: "memory")
#define CP_WAIT2()  asm volatile("cp.async.wait_group 2;" ::: "memory")

#define LDSM_X4(r, addr) \
    asm volatile("ldmatrix.sync.aligned.m8n8.x4.shared.b16 {%0,%1,%2,%3}, [%4];" \
        : "=r"((r)[0]), "=r"((r)[1]), "=r"((r)[2]), "=r"((r)[3]) : "r"(addr))

#define MMA16816(c, a0, a1, a2, a3, b0, b1) \
    asm volatile("mma.sync.aligned.m16n8k16.row.col.f32.bf16.bf16.f32 " \
        "{%0,%1,%2,%3}, {%4,%5,%6,%7}, {%8,%9}, {%0,%1,%2,%3};" \
        : "+f"((c)[0]), "+f"((c)[1]), "+f"((c)[2]), "+f"((c)[3]) \
        : "r"(a0), "r"(a1), "r"(a2), "r"(a3), "r"(b0), "r"(b1))

// ---------------------------------------------------------------------------
// Kernel 1: normalize rows -> fp32 + bf16 copies.
// ---------------------------------------------------------------------------
__global__ void ntx_normalize(const float* __restrict__ zi,
                              const float* __restrict__ zj) {
    const int row = blockIdx.x;
    const int t   = threadIdx.x;             // 0..127
    const float* src = (row < BHALF) ? (zi + (size_t)row * DDIM)
                                     : (zj + (size_t)(row - BHALF) * DDIM);
    float4 v = ((const float4*)src)[t];
    float ss = v.x*v.x + v.y*v.y + v.z*v.z + v.w*v.w;
    #pragma unroll
    for (int o = 16; o > 0; o >>= 1) ss += __shfl_xor_sync(0xffffffffu, ss, o);
    __shared__ float sw[4];
    if ((t & 31) == 0) sw[t >> 5] = ss;
    __syncthreads();
    float tot = sw[0] + sw[1] + sw[2] + sw[3];
    float scale = 1.0f / fmaxf(sqrtf(tot), 1e-12f);
    float4 o4 = make_float4(v.x*scale, v.y*scale, v.z*scale, v.w*scale);
    ((float4*)(g_zn + (size_t)row * DDIM))[t] = o4;
    __nv_bfloat162 h0 = __floats2bfloat162_rn(o4.x, o4.y);
    __nv_bfloat162 h1 = __floats2bfloat162_rn(o4.z, o4.w);
    uint2 pk = make_uint2(*reinterpret_cast<uint32_t*>(&h0),
                          *reinterpret_cast<uint32_t*>(&h1));
    ((uint2*)(g_zbf + (size_t)row * DDIM))[t] = pk;
}

// ---------------------------------------------------------------------------
// Kernel 2: bf16 mma.sync GEMM + exp-sum epilogue.
//   grid = (64, CSPLIT), 256 threads (8 warps, 2x4 warp tile of 64x32).
//   A tile (128x512) resident in SMEM as 8 SW128 chunks of 128x64.
//   B streamed in 128x64 chunks through a 4-stage cp.async ring.
// ---------------------------------------------------------------------------
__global__ __launch_bounds__(256, 1) void ntx_gemm_mma() {
    extern __shared__ char smraw[];
    char* sm = (char*)(((uintptr_t)smraw + 1023) & ~(uintptr_t)1023);
    const uint32_t sbase = smem_u32(sm);
    const uint32_t A0  = sbase;              // 8 x 16KB = 128KB
    const uint32_t Bst = sbase + 131072;     // 4 x 16KB = 64KB
    float* red = (float*)(sm + 131072 + 65536);   // 128 x 4 floats

    const int tid = threadIdx.x;
    const int l   = tid & 31;
    const int wid = tid >> 5;
    const int wm  = wid >> 2;                // 0..1 row half
    const int wn  = wid & 3;                 // 0..3 col quarter
    const int rb    = blockIdx.x * 128;
    const int cbase = blockIdx.y * COLS_PER_CTA;

    // --- prologue: load resident A tile (one commit group) ---
    {
        const int r  = tid >> 1;             // 0..127
        const int hh = tid & 1;
        const char* src = (const char*)(g_zbf + (size_t)(rb + r) * DDIM);
        #pragma unroll
        for (int kc = 0; kc < 8; kc++) {
            #pragma unroll
            for (int q = 0; q < 4; q++) {
                const int cidx = hh * 4 + q;
                uint32_t dst = A0 + kc * 16384u + (uint32_t)r * 128u
                             + (uint32_t)((cidx ^ (r & 7)) << 4);
                cpasync16(dst, src + kc * 128 + cidx * 16);
            }
        }
        CP_COMMIT();
    }

    auto loadB = [&](int c, int stage) {
        const int ct = c >> 3, kc = c & 7;
        const int r  = tid >> 1;
        const int hh = tid & 1;
        const char* src = (const char*)
            (g_zbf + (size_t)(cbase + ct * 128 + r) * DDIM) + kc * 128;
        const uint32_t db = Bst + (uint32_t)stage * 16384u + (uint32_t)r * 128u;
        #pragma unroll
        for (int q = 0; q < 4; q++) {
            const int cidx = hh * 4 + q;
            cpasync16(db + (uint32_t)((cidx ^ (r & 7)) << 4), src + cidx * 16);
        }
    };
    loadB(0, 0); CP_COMMIT();
    loadB(1, 1); CP_COMMIT();
    loadB(2, 2); CP_COMMIT();

    // --- per-lane ldmatrix bases ---
    const uint32_t lx    = (uint32_t)(l & 7);
    const uint32_t a_k16 = (uint32_t)(l >> 4);                       // 0/1
    const uint32_t a_row = (uint32_t)(wm * 64 + ((l >> 3) & 1) * 8 + (l & 7));
    uint32_t a_base[4];
    #pragma unroll
    for (int mt = 0; mt < 4; mt++) a_base[mt] = A0 + (a_row + mt * 16) * 128u;
    const uint32_t b_k16 = (uint32_t)((l >> 3) & 1);                 // 0/1
    const uint32_t b_row = (uint32_t)(wn * 32 + ((l >> 4) & 1) * 8 + (l & 7));
    uint32_t b_off[2];
    #pragma unroll
    for (int p = 0; p < 2; p++) b_off[p] = (b_row + p * 16) * 128u;

    float acc[4][4][4];
    #pragma unroll
    for (int mt = 0; mt < 4; mt++)
        #pragma unroll
        for (int nt = 0; nt < 4; nt++)
            #pragma unroll
            for (int c = 0; c < 4; c++) acc[mt][nt][c] = 0.0f;
    float rs[4][2];
    #pragma unroll
    for (int mt = 0; mt < 4; mt++) { rs[mt][0] = 0.0f; rs[mt][1] = 0.0f; }

    // --- mainloop over 256 B chunks ---
    for (int g = 0; g < NCHUNK; g++) {
        CP_WAIT2();
        __syncthreads();
        if (g + 3 < NCHUNK) loadB(g + 3, (g + 3) & (NSTB - 1));
        CP_COMMIT();

        const int kc = g & 7;
        const uint32_t Akc = (uint32_t)kc * 16384u;
        const uint32_t Bs  = Bst + (uint32_t)(g & (NSTB - 1)) * 16384u;

        #pragma unroll
        for (int ks = 0; ks < 4; ks++) {
            const uint32_t aoffs = (((uint32_t)(ks * 2) + a_k16) ^ lx) << 4;
            const uint32_t boffs = (((uint32_t)(ks * 2) + b_k16) ^ lx) << 4;
            uint32_t a[4][4], b[2][4];
            #pragma unroll
            for (int mt = 0; mt < 4; mt++)
                LDSM_X4(a[mt], a_base[mt] + Akc + aoffs);
            #pragma unroll
            for (int p = 0; p < 2; p++)
                LDSM_X4(b[p], Bs + b_off[p] + boffs);
            #pragma unroll
            for (int mt = 0; mt < 4; mt++) {
                #pragma unroll
                for (int p = 0; p < 2; p++) {
                    MMA16816(acc[mt][p*2+0], a[mt][0], a[mt][1], a[mt][2], a[mt][3],
                             b[p][0], b[p][1]);
                    MMA16816(acc[mt][p*2+1], a[mt][0], a[mt][1], a[mt][2], a[mt][3],
                             b[p][2], b[p][3]);
                }
            }
        }

        if (kc == 7) {
            // epilogue for this 128x128 tile: rs += exp(10*acc - 10)
            #pragma unroll
            for (int mt = 0; mt < 4; mt++) {
                float s0 = 0.0f, s1 = 0.0f;
                #pragma unroll
                for (int nt = 0; nt < 4; nt++) {
                    s0 += __expf(fmaf(acc[mt][nt][0], INV_T, -MSHIFT));
                    s0 += __expf(fmaf(acc[mt][nt][1], INV_T, -MSHIFT));
                    s1 += __expf(fmaf(acc[mt][nt][2], INV_T, -MSHIFT));
                    s1 += __expf(fmaf(acc[mt][nt][3], INV_T, -MSHIFT));
                    acc[mt][nt][0] = 0.0f; acc[mt][nt][1] = 0.0f;
                    acc[mt][nt][2] = 0.0f; acc[mt][nt][3] = 0.0f;
                }
                rs[mt][0] += s0;
                rs[mt][1] += s1;
            }
        }
    }

    // --- final reduction: lanes (l&3) share a row; then 4 wn warps ---
    __syncthreads();
    #pragma unroll
    for (int mt = 0; mt < 4; mt++) {
        #pragma unroll
        for (int h = 0; h < 2; h++) {
            float v = rs[mt][h];
            v += __shfl_xor_sync(0xffffffffu, v, 1);
            v += __shfl_xor_sync(0xffffffffu, v, 2);
            if ((l & 3) == 0) {
                const int row_local = wm * 64 + mt * 16 + (l >> 2) + 8 * h;
                red[row_local * 4 + wn] = v;
            }
        }
    }
    __syncthreads();
    if (tid < 128) {
        float s = red[tid*4+0] + red[tid*4+1] + red[tid*4+2] + red[tid*4+3];
        g_spart[blockIdx.y * NROWS + rb + tid] = s;
    }
}

// ---------------------------------------------------------------------------
// Kernel 3: positives (fp32) + bf16 diagonal correction + per-row loss.
// ---------------------------------------------------------------------------
__global__ void ntx_pairloss() {
    const int p = blockIdx.x;                // 0..BHALF-1
    const int t = threadIdx.x;               // 0..127
    const int q = p + BHALF;
    float4 a = ((const float4*)(g_zn + (size_t)p * DDIM))[t];
    float4 b = ((const float4*)(g_zn + (size_t)q * DDIM))[t];
    float d = a.x*b.x + a.y*b.y + a.z*b.z + a.w*b.w;
    // bf16 self-dots (match tensor-core diagonal terms: exact fp32 products)
    uint2 ua = ((const uint2*)(g_zbf + (size_t)p * DDIM))[t];
    uint2 ub = ((const uint2*)(g_zbf + (size_t)q * DDIM))[t];
    __nv_bfloat162 a0 = *reinterpret_cast<__nv_bfloat162*>(&ua.x);
    __nv_bfloat162 a1 = *reinterpret_cast<__nv_bfloat162*>(&ua.y);
    __nv_bfloat162 b0 = *reinterpret_cast<__nv_bfloat162*>(&ub.x);
    __nv_bfloat162 b1 = *reinterpret_cast<__nv_bfloat162*>(&ub.y);
    float qa = __bfloat162float(a0.x)*__bfloat162float(a0.x)
             + __bfloat162float(a0.y)*__bfloat162float(a0.y)
             + __bfloat162float(a1.x)*__bfloat162float(a1.x)
             + __bfloat162float(a1.y)*__bfloat162float(a1.y);
    float qb = __bfloat162float(b0.x)*__bfloat162float(b0.x)
             + __bfloat162float(b0.y)*__bfloat162float(b0.y)
             + __bfloat162float(b1.x)*__bfloat162float(b1.x)
             + __bfloat162float(b1.y)*__bfloat162float(b1.y);
    #pragma unroll
    for (int o = 16; o > 0; o >>= 1) {
        d  += __shfl_xor_sync(0xffffffffu, d,  o);
        qa += __shfl_xor_sync(0xffffffffu, qa, o);
        qb += __shfl_xor_sync(0xffffffffu, qb, o);
    }
    __shared__ float sw[12];
    if ((t & 31) == 0) { sw[t>>5] = d; sw[4+(t>>5)] = qa; sw[8+(t>>5)] = qb; }
    __syncthreads();
    if (t == 0) {
        float dot = sw[0]+sw[1]+sw[2]+sw[3];
        float qat = sw[4]+sw[5]+sw[6]+sw[7];
        float qbt = sw[8]+sw[9]+sw[10]+sw[11];
        float pos = dot * INV_T;
        float diag_a = expf(fmaf(qat, INV_T, -MSHIFT));
        float diag_b = expf(fmaf(qbt, INV_T, -MSHIFT));
        float s0 = g_spart[0*NROWS + p] + g_spart[1*NROWS + p] - diag_a;
        float s1 = g_spart[0*NROWS + q] + g_spart[1*NROWS + q] - diag_b;
        g_rowloss[p] = MSHIFT + logf(s0) - pos;
        g_rowloss[q] = MSHIFT + logf(s1) - pos;
    }
}

// ---------------------------------------------------------------------------
// Kernel 4: mean over NROWS -> scalar out.
// ---------------------------------------------------------------------------
__global__ void ntx_reduce(float* __restrict__ out) {
    const int t = threadIdx.x;               // 256 threads
    float s = 0.0f;
    for (int i = t; i < NROWS; i += 256) s += g_rowloss[i];
    #pragma unroll
    for (int o = 16; o > 0; o >>= 1) s += __shfl_xor_sync(0xffffffffu, s, o);
    __shared__ float sw[8];
    if ((t & 31) == 0) sw[t >> 5] = s;
    __syncthreads();
    if (t == 0) {
        float tot = 0.0f;
        #pragma unroll
        for (int w = 0; w < 8; w++) tot += sw[w];
        out[0] = tot * (1.0f / (float)NROWS);
    }
}

// ---------------------------------------------------------------------------
#define SMEM_BYTES (1024 + 131072 + 65536 + 2048)

extern "C" void kernel_launch(void* const* d_in, const int* in_sizes, int n_in,
                              void* d_out, int out_size) {
    const float* zi = (const float*)d_in[0];
    const float* zj = (const float*)d_in[1];
    float* out = (float*)d_out;
    (void)in_sizes; (void)n_in; (void)out_size;

    cudaFuncSetAttribute(ntx_gemm_mma,
                         cudaFuncAttributeMaxDynamicSharedMemorySize, SMEM_BYTES);

    ntx_normalize<<<NROWS, 128>>>(zi, zj);
    ntx_gemm_mma<<<dim3(NROWS / 128, CSPLIT), 256, SMEM_BYTES>>>();
    ntx_pairloss<<<BHALF, 128>>>();
    ntx_reduce<<<1, 256>>>(out);
}

// round 6
// speedup vs baseline: 10.7933x; 2.5415x over previous
#include <cuda_runtime.h>
#include <cuda_bf16.h>
#include <math.h>
#include <stdint.h>

// Problem shape (fixed): B=4096, D=512, N=2B=8192, T=0.1
#define BHALF 4096
#define NROWS 8192
#define DDIM  512
#define INV_T 10.0f
#define MSHIFT 10.0f
#define NBLK 64            // 64 row blocks of 128
#define NTILES 2080        // upper-triangle tiles
#define NSTB 4             // B ring stages

// Scratch (__device__ globals: allocation-free rule)
__device__ float         g_zn[NROWS * DDIM];     // fp32 normalized (positives)
__device__ __nv_bfloat16 g_zbf[NROWS * DDIM];    // bf16 normalized (GEMM)
__device__ float         g_rowpart[128 * 2 * 128];  // [cta][phase][row]
__device__ float         g_colpart[NTILES * 128];   // per-tile column sums
__device__ float         g_s[NROWS];                // full row sums
__device__ float         g_rowloss[NROWS];

// ---------------- helpers ----------------
__device__ __forceinline__ uint32_t smem_u32(const void* p) {
    uint32_t a;
    asm("{ .reg .u64 t; cvta.to.shared.u64 t, %1; cvt.u32.u64 %0, t; }" : "=r"(a) : "l"(p));
    return a;
}
__device__ __forceinline__ void cpasync16(uint32_t dst, const void* src) {
    asm volatile("cp.async.cg.shared.global [%0], [%1], 16;" :: "r"(dst), "l"(src) : "memory");
}
#define CP_COMMIT() asm volatile("cp.async.commit_group;" ::: "memory")
#define CP_WAIT2()  asm volatile("cp.async.wait_group 2;" ::: "memory")

#define LDSM_X4(r, addr) \
    asm volatile("ldmatrix.sync.aligned.m8n8.x4.shared.b16 {%0,%1,%2,%3}, [%4];" \
        : "=r"((r)[0]), "=r"((r)[1]), "=r"((r)[2]), "=r"((r)[3]) : "r"(addr))

#define MMA16816(c, a0, a1, a2, a3, b0, b1) \
    asm volatile("mma.sync.aligned.m16n8k16.row.col.f32.bf16.bf16.f32 " \
        "{%0,%1,%2,%3}, {%4,%5,%6,%7}, {%8,%9}, {%0,%1,%2,%3};" \
        : "+f"((c)[0]), "+f"((c)[1]), "+f"((c)[2]), "+f"((c)[3]) \
        : "r"(a0), "r"(a1), "r"(a2), "r"(a3), "r"(b0), "r"(b1))

// global index of upper-triangle tile (i,j), i<=j
__device__ __forceinline__ int tile_index(int i, int j) {
    return i * (129 - i) / 2 + (j - i);
}

// ---------------------------------------------------------------------------
// Kernel 1: normalize rows -> fp32 + bf16 copies.
// ---------------------------------------------------------------------------
__global__ void ntx_normalize(const float* __restrict__ zi,
                              const float* __restrict__ zj) {
    const int row = blockIdx.x;
    const int t   = threadIdx.x;             // 0..127
    const float* src = (row < BHALF) ? (zi + (size_t)row * DDIM)
                                     : (zj + (size_t)(row - BHALF) * DDIM);
    float4 v = ((const float4*)src)[t];
    float ss = v.x*v.x + v.y*v.y + v.z*v.z + v.w*v.w;
    #pragma unroll
    for (int o = 16; o > 0; o >>= 1) ss += __shfl_xor_sync(0xffffffffu, ss, o);
    __shared__ float sw[4];
    if ((t & 31) == 0) sw[t >> 5] = ss;
    __syncthreads();
    float tot = sw[0] + sw[1] + sw[2] + sw[3];
    float scale = 1.0f / fmaxf(sqrtf(tot), 1e-12f);
    float4 o4 = make_float4(v.x*scale, v.y*scale, v.z*scale, v.w*scale);
    ((float4*)(g_zn + (size_t)row * DDIM))[t] = o4;
    __nv_bfloat162 h0 = __floats2bfloat162_rn(o4.x, o4.y);
    __nv_bfloat162 h1 = __floats2bfloat162_rn(o4.z, o4.w);
    uint2 pk = make_uint2(*reinterpret_cast<uint32_t*>(&h0),
                          *reinterpret_cast<uint32_t*>(&h1));
    ((uint2*)(g_zbf + (size_t)row * DDIM))[t] = pk;
}

// ---------------------------------------------------------------------------
// Kernel 2: symmetric bf16 mma.sync GEMM over upper-triangle tiles.
//   grid = (4 quarters, 32 strip-pairs), 256 threads.
//   Pair p handles strips ti=p (64-p tiles) and ti=63-p (p+1 tiles) = 65.
//   Each quarter takes a contiguous span of the 65-tile list (<=2 A loads).
//   Epilogue: rows -> register partials; cols -> per-tile global partials.
// ---------------------------------------------------------------------------
__global__ __launch_bounds__(256, 1) void ntx_gemm_sym() {
    extern __shared__ char smraw[];
    char* sm = (char*)(((uintptr_t)smraw + 1023) & ~(uintptr_t)1023);
    const uint32_t sbase = smem_u32(sm);
    const uint32_t A0  = sbase;                       // 128 KB
    const uint32_t Bst = sbase + 131072;              // 64 KB
    float* red    = (float*)(sm + 131072 + 65536);    // 512 floats
    float* colred = (float*)(sm + 131072 + 65536 + 2048);  // 256 floats

    const int tid = threadIdx.x;
    const int l   = tid & 31;
    const int wid = tid >> 5;
    const int wm  = wid >> 2;                // 0..1 row half
    const int wn  = wid & 3;                 // 0..3 col quarter
    const int q   = blockIdx.x;              // quarter
    const int p   = blockIdx.y;              // strip pair
    const int cta = p * 4 + q;
    const int n0  = NBLK - p;                // tiles in strip p
    const int start = (q * 65) / 4;
    const int end   = ((q + 1) * 65) / 4;

    // per-lane ldmatrix bases (fixed)
    const uint32_t lx    = (uint32_t)(l & 7);
    const uint32_t a_k16 = (uint32_t)(l >> 4);
    const uint32_t a_row = (uint32_t)(wm * 64 + ((l >> 3) & 1) * 8 + (l & 7));
    uint32_t a_base[4];
    #pragma unroll
    for (int mt = 0; mt < 4; mt++) a_base[mt] = A0 + (a_row + mt * 16) * 128u;
    const uint32_t b_k16 = (uint32_t)((l >> 3) & 1);
    const uint32_t b_row = (uint32_t)(wn * 32 + ((l >> 4) & 1) * 8 + (l & 7));
    uint32_t b_off[2];
    #pragma unroll
    for (int pp = 0; pp < 2; pp++) b_off[pp] = (b_row + pp * 16) * 128u;

    float acc[4][4][4];
    #pragma unroll
    for (int mt = 0; mt < 4; mt++)
        #pragma unroll
        for (int nt = 0; nt < 4; nt++)
            #pragma unroll
            for (int c = 0; c < 4; c++) acc[mt][nt][c] = 0.0f;

    for (int phase = 0; phase < 2; phase++) {
        int ti, t0, t1;
        if (phase == 0) {
            ti = p;
            int s = start, e = (end < n0) ? end : n0;
            t0 = p + s; t1 = p + ((e > s) ? e : s);
        } else {
            ti = NBLK - 1 - p;
            int s = (start > n0) ? start : n0, e = end;
            t0 = ti + (s - n0); t1 = ti + ((e > s) ? (e - n0) : (s - n0));
        }
        const int ntiles = t1 - t0;
        const int nch = ntiles * 8;

        float rs[4][2];
        #pragma unroll
        for (int mt = 0; mt < 4; mt++) { rs[mt][0] = 0.0f; rs[mt][1] = 0.0f; }

        if (ntiles > 0) {
            const int rb = ti * 128;
            // --- A tile load (one group) ---
            {
                const int r  = tid >> 1;
                const int hh = tid & 1;
                const char* src = (const char*)(g_zbf + (size_t)(rb + r) * DDIM);
                #pragma unroll
                for (int kc = 0; kc < 8; kc++) {
                    #pragma unroll
                    for (int qq = 0; qq < 4; qq++) {
                        const int cidx = hh * 4 + qq;
                        uint32_t dst = A0 + kc * 16384u + (uint32_t)r * 128u
                                     + (uint32_t)((cidx ^ (r & 7)) << 4);
                        cpasync16(dst, src + kc * 128 + cidx * 16);
                    }
                }
                CP_COMMIT();
            }

            auto loadB = [&](int c, int stage) {
                const int tj = t0 + (c >> 3), kc = c & 7;
                const int r  = tid >> 1;
                const int hh = tid & 1;
                const char* src = (const char*)
                    (g_zbf + (size_t)(tj * 128 + r) * DDIM) + kc * 128;
                const uint32_t db = Bst + (uint32_t)stage * 16384u + (uint32_t)r * 128u;
                #pragma unroll
                for (int qq = 0; qq < 4; qq++) {
                    const int cidx = hh * 4 + qq;
                    cpasync16(db + (uint32_t)((cidx ^ (r & 7)) << 4), src + cidx * 16);
                }
            };
            loadB(0, 0); CP_COMMIT();
            if (nch > 1) loadB(1, 1); CP_COMMIT();
            if (nch > 2) loadB(2, 2); CP_COMMIT();

            for (int g = 0; g < nch; g++) {
                CP_WAIT2();
                __syncthreads();
                if (g + 3 < nch) loadB(g + 3, (g + 3) & (NSTB - 1));
                CP_COMMIT();

                const int kc = g & 7;
                const uint32_t Akc = (uint32_t)kc * 16384u;
                const uint32_t Bs  = Bst + (uint32_t)(g & (NSTB - 1)) * 16384u;

                #pragma unroll
                for (int ks = 0; ks < 4; ks++) {
                    const uint32_t aoffs = (((uint32_t)(ks * 2) + a_k16) ^ lx) << 4;
                    const uint32_t boffs = (((uint32_t)(ks * 2) + b_k16) ^ lx) << 4;
                    uint32_t a[4][4], b[2][4];
                    #pragma unroll
                    for (int mt = 0; mt < 4; mt++)
                        LDSM_X4(a[mt], a_base[mt] + Akc + aoffs);
                    #pragma unroll
                    for (int pp = 0; pp < 2; pp++)
                        LDSM_X4(b[pp], Bs + b_off[pp] + boffs);
                    #pragma unroll
                    for (int mt = 0; mt < 4; mt++) {
                        #pragma unroll
                        for (int pp = 0; pp < 2; pp++) {
                            MMA16816(acc[mt][pp*2+0], a[mt][0], a[mt][1], a[mt][2], a[mt][3],
                                     b[pp][0], b[pp][1]);
                            MMA16816(acc[mt][pp*2+1], a[mt][0], a[mt][1], a[mt][2], a[mt][3],
                                     b[pp][2], b[pp][3]);
                        }
                    }
                }

                if (kc == 7) {
                    const int tj = t0 + (g >> 3);
                    // element-wise exp -> row partials (regs) + col partials
                    float cs[4][2];
                    #pragma unroll
                    for (int nt = 0; nt < 4; nt++) { cs[nt][0] = 0.0f; cs[nt][1] = 0.0f; }
                    #pragma unroll
                    for (int mt = 0; mt < 4; mt++) {
                        #pragma unroll
                        for (int nt = 0; nt < 4; nt++) {
                            float e0 = __expf(fmaf(acc[mt][nt][0], INV_T, -MSHIFT));
                            float e1 = __expf(fmaf(acc[mt][nt][1], INV_T, -MSHIFT));
                            float e2 = __expf(fmaf(acc[mt][nt][2], INV_T, -MSHIFT));
                            float e3 = __expf(fmaf(acc[mt][nt][3], INV_T, -MSHIFT));
                            rs[mt][0] += e0 + e1;
                            rs[mt][1] += e2 + e3;
                            cs[nt][0] += e0 + e2;
                            cs[nt][1] += e1 + e3;
                            acc[mt][nt][0] = 0.0f; acc[mt][nt][1] = 0.0f;
                            acc[mt][nt][2] = 0.0f; acc[mt][nt][3] = 0.0f;
                        }
                    }
                    // reduce cols across the 8 row-lane groups (strides 4,8,16)
                    #pragma unroll
                    for (int off = 4; off <= 16; off <<= 1)
                        #pragma unroll
                        for (int nt = 0; nt < 4; nt++) {
                            cs[nt][0] += __shfl_xor_sync(0xffffffffu, cs[nt][0], off);
                            cs[nt][1] += __shfl_xor_sync(0xffffffffu, cs[nt][1], off);
                        }
                    if (l < 4) {
                        #pragma unroll
                        for (int nt = 0; nt < 4; nt++) {
                            const int colb = wn * 32 + (nt >> 1) * 16 + (nt & 1) * 8 + 2 * l;
                            colred[wm * 128 + colb    ] = cs[nt][0];
                            colred[wm * 128 + colb + 1] = cs[nt][1];
                        }
                    }
                    __syncthreads();
                    if (ti != tj && tid < 128) {
                        const int gidx = tile_index(ti, tj);
                        g_colpart[(size_t)gidx * 128 + tid] =
                            colred[tid] + colred[128 + tid];
                    }
                }
            }
        }

        // --- store row partials for this phase (zeros if empty) ---
        __syncthreads();
        #pragma unroll
        for (int mt = 0; mt < 4; mt++) {
            #pragma unroll
            for (int h = 0; h < 2; h++) {
                float v = rs[mt][h];
                v += __shfl_xor_sync(0xffffffffu, v, 1);
                v += __shfl_xor_sync(0xffffffffu, v, 2);
                if ((l & 3) == 0) {
                    const int row_local = wm * 64 + mt * 16 + (l >> 2) + 8 * h;
                    red[row_local * 4 + wn] = v;
                }
            }
        }
        __syncthreads();
        if (tid < 128) {
            float s = red[tid*4+0] + red[tid*4+1] + red[tid*4+2] + red[tid*4+3];
            g_rowpart[(size_t)(cta * 2 + phase) * 128 + tid] = s;
        }
        __syncthreads();
    }
}

// ---------------------------------------------------------------------------
// Kernel 3: combine row partials + transposed column partials -> g_s.
// ---------------------------------------------------------------------------
__global__ void ntx_rowsum() {
    const int r  = blockIdx.x * 128 + threadIdx.x;
    const int b  = r >> 7;
    const int rl = r & 127;
    const int pair  = (b < 32) ? b : (NBLK - 1 - b);
    const int phase = (b < 32) ? 0 : 1;
    float s = 0.0f;
    #pragma unroll
    for (int qq = 0; qq < 4; qq++)
        s += g_rowpart[(size_t)((pair * 4 + qq) * 2 + phase) * 128 + rl];
    for (int i = 0; i < b; i++)
        s += g_colpart[(size_t)tile_index(i, b) * 128 + rl];
    g_s[r] = s;
}

// ---------------------------------------------------------------------------
// Kernel 4: positives (fp32) + bf16 diagonal correction + per-row loss.
// ---------------------------------------------------------------------------
__global__ void ntx_pairloss() {
    const int p = blockIdx.x;                // 0..BHALF-1
    const int t = threadIdx.x;               // 0..127
    const int q = p + BHALF;
    float4 a = ((const float4*)(g_zn + (size_t)p * DDIM))[t];
    float4 b = ((const float4*)(g_zn + (size_t)q * DDIM))[t];
    float d = a.x*b.x + a.y*b.y + a.z*b.z + a.w*b.w;
    uint2 ua = ((const uint2*)(g_zbf + (size_t)p * DDIM))[t];
    uint2 ub = ((const uint2*)(g_zbf + (size_t)q * DDIM))[t];
    __nv_bfloat162 a0 = *reinterpret_cast<__nv_bfloat162*>(&ua.x);
    __nv_bfloat162 a1 = *reinterpret_cast<__nv_bfloat162*>(&ua.y);
    __nv_bfloat162 b0 = *reinterpret_cast<__nv_bfloat162*>(&ub.x);
    __nv_bfloat162 b1 = *reinterpret_cast<__nv_bfloat162*>(&ub.y);
    float qa = __bfloat162float(a0.x)*__bfloat162float(a0.x)
             + __bfloat162float(a0.y)*__bfloat162float(a0.y)
             + __bfloat162float(a1.x)*__bfloat162float(a1.x)
             + __bfloat162float(a1.y)*__bfloat162float(a1.y);
    float qb = __bfloat162float(b0.x)*__bfloat162float(b0.x)
             + __bfloat162float(b0.y)*__bfloat162float(b0.y)
             + __bfloat162float(b1.x)*__bfloat162float(b1.x)
             + __bfloat162float(b1.y)*__bfloat162float(b1.y);
    #pragma unroll
    for (int o = 16; o > 0; o >>= 1) {
        d  += __shfl_xor_sync(0xffffffffu, d,  o);
        qa += __shfl_xor_sync(0xffffffffu, qa, o);
        qb += __shfl_xor_sync(0xffffffffu, qb, o);
    }
    __shared__ float sw[12];
    if ((t & 31) == 0) { sw[t>>5] = d; sw[4+(t>>5)] = qa; sw[8+(t>>5)] = qb; }
    __syncthreads();
    if (t == 0) {
        float dot = sw[0]+sw[1]+sw[2]+sw[3];
        float qat = sw[4]+sw[5]+sw[6]+sw[7];
        float qbt = sw[8]+sw[9]+sw[10]+sw[11];
        float pos = dot * INV_T;
        float diag_a = expf(fmaf(qat, INV_T, -MSHIFT));
        float diag_b = expf(fmaf(qbt, INV_T, -MSHIFT));
        float s0 = g_s[p] - diag_a;
        float s1 = g_s[q] - diag_b;
        g_rowloss[p] = MSHIFT + logf(s0) - pos;
        g_rowloss[q] = MSHIFT + logf(s1) - pos;
    }
}

// ---------------------------------------------------------------------------
// Kernel 5: mean over NROWS -> scalar out.
// ---------------------------------------------------------------------------
__global__ void ntx_reduce(float* __restrict__ out) {
    const int t = threadIdx.x;               // 256 threads
    float s = 0.0f;
    for (int i = t; i < NROWS; i += 256) s += g_rowloss[i];
    #pragma unroll
    for (int o = 16; o > 0; o >>= 1) s += __shfl_xor_sync(0xffffffffu, s, o);
    __shared__ float sw[8];
    if ((t & 31) == 0) sw[t >> 5] = s;
    __syncthreads();
    if (t == 0) {
        float tot = 0.0f;
        #pragma unroll
        for (int w = 0; w < 8; w++) tot += sw[w];
        out[0] = tot * (1.0f / (float)NROWS);
    }
}

// ---------------------------------------------------------------------------
#define SMEM_BYTES (1024 + 131072 + 65536 + 2048 + 1024)

extern "C" void kernel_launch(void* const* d_in, const int* in_sizes, int n_in,
                              void* d_out, int out_size) {
    const float* zi = (const float*)d_in[0];
    const float* zj = (const float*)d_in[1];
    float* out = (float*)d_out;
    (void)in_sizes; (void)n_in; (void)out_size;

    cudaFuncSetAttribute(ntx_gemm_sym,
                         cudaFuncAttributeMaxDynamicSharedMemorySize, SMEM_BYTES);

    ntx_normalize<<<NROWS, 128>>>(zi, zj);
    ntx_gemm_sym<<<dim3(4, 32), 256, SMEM_BYTES>>>();
    ntx_rowsum<<<NBLK, 128>>>();
    ntx_pairloss<<<BHALF, 128>>>();
    ntx_reduce<<<1, 256>>>(out);
}

// round 7
// speedup vs baseline: 11.3385x; 1.0505x over previous
#include <cuda_runtime.h>
#include <cuda_bf16.h>
#include <cuda_fp8.h>
#include <math.h>
#include <stdint.h>

// Problem shape (fixed): B=4096, D=512, N=2B=8192, T=0.1
#define BHALF 4096
#define NROWS 8192
#define DDIM  512
#define INV_T 10.0f
#define MSHIFT 10.0f
#define QS    16.0f                 // quantization scale: q = e4m3(16*z)
#define EPSC  (10.0f / 256.0f)      // logit = acc * 10 / QS^2
#define NBLK 64                     // 64 row blocks of 128
#define NTILES 2080                 // upper-triangle tiles
#define NSTB 4                      // B ring stages
#define CPT 4                       // chunks per tile (fp8: 4 x 128B of K)

// Scratch (__device__ globals: allocation-free rule)
__device__ uint8_t g_zq[NROWS * DDIM];            // e4m3(16 * zhat), 4.2 MB
__device__ float   g_pos[BHALF];                  // positive logits (fp32)
__device__ float   g_diag[NROWS];                 // exp(diag logit - 10)
__device__ float   g_rowpart[128 * 2 * 128];      // [cta][phase][row]
__device__ float   g_colpart[NTILES * 128];       // per-tile column sums
__device__ float   g_rowloss[NROWS];

// ---------------- helpers ----------------
__device__ __forceinline__ uint32_t smem_u32(const void* p) {
    uint32_t a;
    asm("{ .reg .u64 t; cvta.to.shared.u64 t, %1; cvt.u32.u64 %0, t; }" : "=r"(a) : "l"(p));
    return a;
}
__device__ __forceinline__ void cpasync16(uint32_t dst, const void* src) {
    asm volatile("cp.async.cg.shared.global [%0], [%1], 16;" :: "r"(dst), "l"(src) : "memory");
}
#define CP_COMMIT() asm volatile("cp.async.commit_group;" ::: "memory")
#define CP_WAIT2()  asm volatile("cp.async.wait_group 2;" ::: "memory")

#define LDSM_X4(r, addr) \
    asm volatile("ldmatrix.sync.aligned.m8n8.x4.shared.b16 {%0,%1,%2,%3}, [%4];" \
        : "=r"((r)[0]), "=r"((r)[1]), "=r"((r)[2]), "=r"((r)[3]) : "r"(addr))

#define MMA16832F8(c, a0, a1, a2, a3, b0, b1) \
    asm volatile("mma.sync.aligned.m16n8k32.row.col.f32.e4m3.e4m3.f32 " \
        "{%0,%1,%2,%3}, {%4,%5,%6,%7}, {%8,%9}, {%0,%1,%2,%3};" \
        : "+f"((c)[0]), "+f"((c)[1]), "+f"((c)[2]), "+f"((c)[3]) \
        : "r"(a0), "r"(a1), "r"(a2), "r"(a3), "r"(b0), "r"(b1))

// global index of upper-triangle tile (i,j), i<=j
__device__ __forceinline__ int tile_index(int i, int j) {
    return i * (129 - i) / 2 + (j - i);
}

// ---------------------------------------------------------------------------
// Kernel 1: fused normalize + quantize + positive-dot + diagonal correction.
//   grid = BHALF blocks (one per pair), 128 threads.
// ---------------------------------------------------------------------------
__global__ void ntx_norm_pair(const float* __restrict__ zi,
                              const float* __restrict__ zj) {
    const int p = blockIdx.x;
    const int t = threadIdx.x;               // 0..127, 4 floats of each row
    float4 a = ((const float4*)(zi + (size_t)p * DDIM))[t];
    float4 b = ((const float4*)(zj + (size_t)p * DDIM))[t];
    float ssa = a.x*a.x + a.y*a.y + a.z*a.z + a.w*a.w;
    float ssb = b.x*b.x + b.y*b.y + b.z*b.z + b.w*b.w;
    float dab = a.x*b.x + a.y*b.y + a.z*b.z + a.w*b.w;
    #pragma unroll
    for (int o = 16; o > 0; o >>= 1) {
        ssa += __shfl_xor_sync(0xffffffffu, ssa, o);
        ssb += __shfl_xor_sync(0xffffffffu, ssb, o);
        dab += __shfl_xor_sync(0xffffffffu, dab, o);
    }
    __shared__ float sw[12];
    if ((t & 31) == 0) { sw[t>>5] = ssa; sw[4+(t>>5)] = ssb; sw[8+(t>>5)] = dab; }
    __syncthreads();
    float sa = 1.0f / fmaxf(sqrtf(sw[0]+sw[1]+sw[2]+sw[3]), 1e-12f);
    float sb = 1.0f / fmaxf(sqrtf(sw[4]+sw[5]+sw[6]+sw[7]), 1e-12f);

    // quantize 4 components of each row; accumulate dequantized self-dots
    float fa[4] = { a.x*sa*QS, a.y*sa*QS, a.z*sa*QS, a.w*sa*QS };
    float fb[4] = { b.x*sb*QS, b.y*sb*QS, b.z*sb*QS, b.w*sb*QS };
    uint32_t pka = 0, pkb = 0;
    float qa = 0.0f, qb = 0.0f;
    #pragma unroll
    for (int c = 0; c < 4; c++) {
        __nv_fp8_e4m3 ea(fa[c]);
        __nv_fp8_e4m3 eb(fb[c]);
        float da = float(ea), db = float(eb);
        qa += da * da;  qb += db * db;
        pka |= (uint32_t)ea.__x << (8 * c);
        pkb |= (uint32_t)eb.__x << (8 * c);
    }
    ((uint32_t*)(g_zq + (size_t)p * DDIM))[t] = pka;
    ((uint32_t*)(g_zq + (size_t)(p + BHALF) * DDIM))[t] = pkb;

    #pragma unroll
    for (int o = 16; o > 0; o >>= 1) {
        qa += __shfl_xor_sync(0xffffffffu, qa, o);
        qb += __shfl_xor_sync(0xffffffffu, qb, o);
    }
    __shared__ float sq[8];
    if ((t & 31) == 0) { sq[t>>5] = qa; sq[4+(t>>5)] = qb; }
    __syncthreads();
    if (t == 0) {
        float dot = sw[8]+sw[9]+sw[10]+sw[11];
        float qat = sq[0]+sq[1]+sq[2]+sq[3];
        float qbt = sq[4]+sq[5]+sq[6]+sq[7];
        g_pos[p] = dot * sa * sb * INV_T;
        g_diag[p]         = expf(fmaf(qat, EPSC, -MSHIFT));
        g_diag[p + BHALF] = expf(fmaf(qbt, EPSC, -MSHIFT));
    }
}

// ---------------------------------------------------------------------------
// Kernel 2: symmetric fp8 mma.sync GEMM over upper-triangle tiles.
//   grid = (4 quarters, 32 strip-pairs), 256 threads.
//   fp8 rows are 512B; each 128x128 tile needs 4 K-chunks of 128B.
// ---------------------------------------------------------------------------
__global__ __launch_bounds__(256, 1) void ntx_gemm_sym() {
    extern __shared__ char smraw[];
    char* sm = (char*)(((uintptr_t)smraw + 1023) & ~(uintptr_t)1023);
    const uint32_t sbase = smem_u32(sm);
    const uint32_t A0  = sbase;                       // 4 x 16KB = 64 KB
    const uint32_t Bst = sbase + 65536;               // 4 x 16KB = 64 KB
    float* red    = (float*)(sm + 65536 + 65536);     // 512 floats
    float* colred = (float*)(sm + 65536 + 65536 + 2048);  // 256 floats

    const int tid = threadIdx.x;
    const int l   = tid & 31;
    const int wid = tid >> 5;
    const int wm  = wid >> 2;                // 0..1 row half
    const int wn  = wid & 3;                 // 0..3 col quarter
    const int q   = blockIdx.x;              // quarter
    const int p   = blockIdx.y;              // strip pair
    const int cta = p * 4 + q;
    const int n0  = NBLK - p;                // tiles in strip p
    const int start = (q * 65) / 4;
    const int end   = ((q + 1) * 65) / 4;

    // per-lane ldmatrix bases (fp8 m16n8k32 fragments: same byte wiring as bf16)
    const uint32_t lx    = (uint32_t)(l & 7);
    const uint32_t a_k16 = (uint32_t)(l >> 4);
    const uint32_t a_row = (uint32_t)(wm * 64 + ((l >> 3) & 1) * 8 + (l & 7));
    uint32_t a_base[4];
    #pragma unroll
    for (int mt = 0; mt < 4; mt++) a_base[mt] = A0 + (a_row + mt * 16) * 128u;
    const uint32_t b_k16 = (uint32_t)((l >> 3) & 1);
    const uint32_t b_row = (uint32_t)(wn * 32 + ((l >> 4) & 1) * 8 + (l & 7));
    uint32_t b_off[2];
    #pragma unroll
    for (int pp = 0; pp < 2; pp++) b_off[pp] = (b_row + pp * 16) * 128u;

    float acc[4][4][4];
    #pragma unroll
    for (int mt = 0; mt < 4; mt++)
        #pragma unroll
        for (int nt = 0; nt < 4; nt++)
            #pragma unroll
            for (int c = 0; c < 4; c++) acc[mt][nt][c] = 0.0f;

    for (int phase = 0; phase < 2; phase++) {
        int ti, t0, t1;
        if (phase == 0) {
            ti = p;
            int s = start, e = (end < n0) ? end : n0;
            t0 = p + s; t1 = p + ((e > s) ? e : s);
        } else {
            ti = NBLK - 1 - p;
            int s = (start > n0) ? start : n0, e = end;
            t0 = ti + (s - n0); t1 = ti + ((e > s) ? (e - n0) : (s - n0));
        }
        const int ntiles = t1 - t0;
        const int nch = ntiles * CPT;

        float rs[4][2];
        #pragma unroll
        for (int mt = 0; mt < 4; mt++) { rs[mt][0] = 0.0f; rs[mt][1] = 0.0f; }

        if (ntiles > 0) {
            const int rb = ti * 128;
            // --- A tile load: 128 rows x 512B = 4 chunks (one group) ---
            {
                const int r  = tid >> 1;
                const int hh = tid & 1;
                const char* src = (const char*)(g_zq + (size_t)(rb + r) * DDIM);
                #pragma unroll
                for (int kc = 0; kc < CPT; kc++) {
                    #pragma unroll
                    for (int qq = 0; qq < 4; qq++) {
                        const int cidx = hh * 4 + qq;
                        uint32_t dst = A0 + kc * 16384u + (uint32_t)r * 128u
                                     + (uint32_t)((cidx ^ (r & 7)) << 4);
                        cpasync16(dst, src + kc * 128 + cidx * 16);
                    }
                }
                CP_COMMIT();
            }

            auto loadB = [&](int c, int stage) {
                const int tj = t0 + (c >> 2), kc = c & 3;
                const int r  = tid >> 1;
                const int hh = tid & 1;
                const char* src = (const char*)
                    (g_zq + (size_t)(tj * 128 + r) * DDIM) + kc * 128;
                const uint32_t db = Bst + (uint32_t)stage * 16384u + (uint32_t)r * 128u;
                #pragma unroll
                for (int qq = 0; qq < 4; qq++) {
                    const int cidx = hh * 4 + qq;
                    cpasync16(db + (uint32_t)((cidx ^ (r & 7)) << 4), src + cidx * 16);
                }
            };
            loadB(0, 0); CP_COMMIT();
            if (nch > 1) loadB(1, 1); CP_COMMIT();
            if (nch > 2) loadB(2, 2); CP_COMMIT();

            for (int g = 0; g < nch; g++) {
                CP_WAIT2();
                __syncthreads();
                if (g + 3 < nch) loadB(g + 3, (g + 3) & (NSTB - 1));
                CP_COMMIT();

                const int kc = g & 3;
                const uint32_t Akc = (uint32_t)kc * 16384u;
                const uint32_t Bs  = Bst + (uint32_t)(g & (NSTB - 1)) * 16384u;

                #pragma unroll
                for (int ks = 0; ks < 4; ks++) {      // 4 x k32 per 128B chunk
                    const uint32_t aoffs = (((uint32_t)(ks * 2) + a_k16) ^ lx) << 4;
                    const uint32_t boffs = (((uint32_t)(ks * 2) + b_k16) ^ lx) << 4;
                    uint32_t a[4][4], b[2][4];
                    #pragma unroll
                    for (int mt = 0; mt < 4; mt++)
                        LDSM_X4(a[mt], a_base[mt] + Akc + aoffs);
                    #pragma unroll
                    for (int pp = 0; pp < 2; pp++)
                        LDSM_X4(b[pp], Bs + b_off[pp] + boffs);
                    #pragma unroll
                    for (int mt = 0; mt < 4; mt++) {
                        #pragma unroll
                        for (int pp = 0; pp < 2; pp++) {
                            MMA16832F8(acc[mt][pp*2+0], a[mt][0], a[mt][1], a[mt][2], a[mt][3],
                                       b[pp][0], b[pp][1]);
                            MMA16832F8(acc[mt][pp*2+1], a[mt][0], a[mt][1], a[mt][2], a[mt][3],
                                       b[pp][2], b[pp][3]);
                        }
                    }
                }

                if (kc == CPT - 1) {
                    const int tj = t0 + (g >> 2);
                    float cs[4][2];
                    #pragma unroll
                    for (int nt = 0; nt < 4; nt++) { cs[nt][0] = 0.0f; cs[nt][1] = 0.0f; }
                    #pragma unroll
                    for (int mt = 0; mt < 4; mt++) {
                        #pragma unroll
                        for (int nt = 0; nt < 4; nt++) {
                            float e0 = __expf(fmaf(acc[mt][nt][0], EPSC, -MSHIFT));
                            float e1 = __expf(fmaf(acc[mt][nt][1], EPSC, -MSHIFT));
                            float e2 = __expf(fmaf(acc[mt][nt][2], EPSC, -MSHIFT));
                            float e3 = __expf(fmaf(acc[mt][nt][3], EPSC, -MSHIFT));
                            rs[mt][0] += e0 + e1;
                            rs[mt][1] += e2 + e3;
                            cs[nt][0] += e0 + e2;
                            cs[nt][1] += e1 + e3;
                            acc[mt][nt][0] = 0.0f; acc[mt][nt][1] = 0.0f;
                            acc[mt][nt][2] = 0.0f; acc[mt][nt][3] = 0.0f;
                        }
                    }
                    #pragma unroll
                    for (int off = 4; off <= 16; off <<= 1)
                        #pragma unroll
                        for (int nt = 0; nt < 4; nt++) {
                            cs[nt][0] += __shfl_xor_sync(0xffffffffu, cs[nt][0], off);
                            cs[nt][1] += __shfl_xor_sync(0xffffffffu, cs[nt][1], off);
                        }
                    if (l < 4) {
                        #pragma unroll
                        for (int nt = 0; nt < 4; nt++) {
                            const int colb = wn * 32 + (nt >> 1) * 16 + (nt & 1) * 8 + 2 * l;
                            colred[wm * 128 + colb    ] = cs[nt][0];
                            colred[wm * 128 + colb + 1] = cs[nt][1];
                        }
                    }
                    __syncthreads();
                    if (ti != tj && tid < 128) {
                        const int gidx = tile_index(ti, tj);
                        g_colpart[(size_t)gidx * 128 + tid] =
                            colred[tid] + colred[128 + tid];
                    }
                }
            }
        }

        // --- store row partials for this phase (zeros if empty) ---
        __syncthreads();
        #pragma unroll
        for (int mt = 0; mt < 4; mt++) {
            #pragma unroll
            for (int h = 0; h < 2; h++) {
                float v = rs[mt][h];
                v += __shfl_xor_sync(0xffffffffu, v, 1);
                v += __shfl_xor_sync(0xffffffffu, v, 2);
                if ((l & 3) == 0) {
                    const int row_local = wm * 64 + mt * 16 + (l >> 2) + 8 * h;
                    red[row_local * 4 + wn] = v;
                }
            }
        }
        __syncthreads();
        if (tid < 128) {
            float s = red[tid*4+0] + red[tid*4+1] + red[tid*4+2] + red[tid*4+3];
            g_rowpart[(size_t)(cta * 2 + phase) * 128 + tid] = s;
        }
        __syncthreads();
    }
}

// ---------------------------------------------------------------------------
// Kernel 3: combine partials -> per-row loss.
// ---------------------------------------------------------------------------
__global__ void ntx_rowsum_loss() {
    const int r  = blockIdx.x * 128 + threadIdx.x;
    const int b  = r >> 7;
    const int rl = r & 127;
    const int pair  = (b < 32) ? b : (NBLK - 1 - b);
    const int phase = (b < 32) ? 0 : 1;
    float s = 0.0f;
    #pragma unroll
    for (int qq = 0; qq < 4; qq++)
        s += g_rowpart[(size_t)((pair * 4 + qq) * 2 + phase) * 128 + rl];
    for (int i = 0; i < b; i++)
        s += g_colpart[(size_t)tile_index(i, b) * 128 + rl];
    const float pos = g_pos[r & (BHALF - 1)];
    g_rowloss[r] = MSHIFT + logf(s - g_diag[r]) - pos;
}

// ---------------------------------------------------------------------------
// Kernel 4: mean over NROWS -> scalar out.
// ---------------------------------------------------------------------------
__global__ void ntx_reduce(float* __restrict__ out) {
    const int t = threadIdx.x;               // 256 threads
    float s = 0.0f;
    for (int i = t; i < NROWS; i += 256) s += g_rowloss[i];
    #pragma unroll
    for (int o = 16; o > 0; o >>= 1) s += __shfl_xor_sync(0xffffffffu, s, o);
    __shared__ float sw[8];
    if ((t & 31) == 0) sw[t >> 5] = s;
    __syncthreads();
    if (t == 0) {
        float tot = 0.0f;
        #pragma unroll
        for (int w = 0; w < 8; w++) tot += sw[w];
        out[0] = tot * (1.0f / (float)NROWS);
    }
}

// ---------------------------------------------------------------------------
#define SMEM_BYTES (1024 + 65536 + 65536 + 2048 + 1024)

extern "C" void kernel_launch(void* const* d_in, const int* in_sizes, int n_in,
                              void* d_out, int out_size) {
    const float* zi = (const float*)d_in[0];
    const float* zj = (const float*)d_in[1];
    float* out = (float*)d_out;
    (void)in_sizes; (void)n_in; (void)out_size;

    cudaFuncSetAttribute(ntx_gemm_sym,
                         cudaFuncAttributeMaxDynamicSharedMemorySize, SMEM_BYTES);

    ntx_norm_pair<<<BHALF, 128>>>(zi, zj);
    ntx_gemm_sym<<<dim3(4, 32), 256, SMEM_BYTES>>>();
    ntx_rowsum_loss<<<NBLK, 128>>>();
    ntx_reduce<<<1, 256>>>(out);
}